// round 5
// baseline (speedup 1.0000x reference)
#include <cuda_runtime.h>
#include <cuda_bf16.h>

// ---------------- problem constants ----------------
#define BATCH   4
#define NPTS    32768
#define NCLS    3
#define KSEL    4096          // NMS_PRE_MAXSIZE
#define KPOST   512           // NMS_POST_MAXSIZE
#define NWORDS  64            // 4096 / 64
#define NW1     16            // stage-0 scan: first 1024 boxes
#define NBUCK   65536         // 16-bit score-radix buckets

#define ROIS_ELEMS   (BATCH * KPOST * 7)          // 14336
#define SC_OFF       (ROIS_ELEMS)                 // 14336
#define LB_OFF       (ROIS_ELEMS + BATCH * KPOST) // 16384

// ---------------- device scratch (no allocations allowed) ----------------
__device__ unsigned long long g_keyfull[BATCH][NPTS];       // 1 MB
__device__ unsigned long long g_cand[BATCH][NPTS];          // 1 MB (bucket-grouped)
__device__ int                g_hist[BATCH][NBUCK];         // 1 MB
__device__ int                g_base[BATCH][NBUCK];         // 1 MB (static suffix counts)
__device__ int                g_basedyn[BATCH][NBUCK];      // 1 MB (scatter cursors)
__device__ int                g_candcnt[BATCH];

__device__ float4             g_box4[BATCH][KSEL];          // x1,y1,x2,y2
__device__ float              g_area[BATCH][KSEL];
__device__ float              g_rois[BATCH][KSEL][7];
__device__ float              g_scores[BATCH][KSEL];
__device__ unsigned char      g_labels[BATCH][KSEL];
__device__ unsigned long long g_mask0[BATCH][1024 * NW1];   // 512 KB, stage-0 mask [row][word]
__device__ unsigned long long g_accept[BATCH][NWORDS];

// ---------------- helpers ----------------
__device__ __forceinline__ unsigned f2ord(float s) {
    unsigned u = __float_as_uint(s);
    return (u & 0x80000000u) ? ~u : (u | 0x80000000u);
}

// exact-rounding IOU>thresh test, identical op order to reference
__device__ __forceinline__ bool iou_gt(float4 A, float aA, float4 B, float aB) {
    float ix = __fsub_rn(fminf(A.z, B.z), fmaxf(A.x, B.x));
    float iy = __fsub_rn(fminf(A.w, B.w), fmaxf(A.y, B.y));
    if (ix > 0.0f && iy > 0.0f) {
        float inter = __fmul_rn(ix, iy);
        float denom = __fadd_rn(__fsub_rn(__fadd_rn(aA, aB), inter), 1e-6f);
        return __fdiv_rn(inter, denom) > 0.7f;
    }
    return false;
}

// ---------------- K0: zero histogram + candcnt ----------------
__global__ void k_zero_state() {
    int i = blockIdx.x * blockDim.x + threadIdx.x;
    int stride = gridDim.x * blockDim.x;
    int4 z = make_int4(0, 0, 0, 0);
    int4* h4 = (int4*)g_hist;
    const int n4 = BATCH * NBUCK / 4;
    for (int e = i; e < n4; e += stride) h4[e] = z;
    if (i < BATCH) g_candcnt[i] = 0;
}

// ---------------- K1: keys + 16-bit bucket histogram ----------------
__global__ void k_keys_hist(const float* __restrict__ cls) {
    int g = blockIdx.x * blockDim.x + threadIdx.x;      // 0 .. BATCH*NPTS-1
    if (g >= BATCH * NPTS) return;
    int b = g >> 15, i = g & (NPTS - 1);
    const float* cp = cls + (size_t)g * NCLS;
    float s = fmaxf(fmaxf(cp[0], cp[1]), cp[2]);
    unsigned u = f2ord(s);
    unsigned long long key = ((unsigned long long)u << 32) |
                             (unsigned long long)(0xFFFFFFFFu - (unsigned)i);
    g_keyfull[b][i] = key;
    atomicAdd(&g_hist[b][u >> 16], 1);
}

// ---------------- K2: suffix-scan -> base[bucket] (x2), candcnt ----------------
__global__ void __launch_bounds__(1024)
k_scan_hist() {
    __shared__ int s[1024];
    __shared__ int smax;
    int b = blockIdx.x, t = threadIdx.x;
    if (t == 0) smax = 0;

    int h[64];
    int sum = 0;
    const int b0 = t * 64;
#pragma unroll
    for (int k = 0; k < 64; k++) { h[k] = g_hist[b][b0 + k]; sum += h[k]; }
    int own = sum;
    s[t] = sum;
    __syncthreads();
    for (int d = 1; d < 1024; d <<= 1) {
        int v = (t + d < 1024) ? s[t + d] : 0;
        __syncthreads();
        s[t] += v;
        __syncthreads();
    }
    int run = s[t] - own;            // strictly-above count for bucket b0+63
    int localmax = 0;
#pragma unroll
    for (int k = 63; k >= 0; k--) {
        g_base[b][b0 + k]    = run;
        g_basedyn[b][b0 + k] = run;  // scatter cursor starts at base
        if (run < KSEL && h[k] > 0) {
            int e = run + h[k];
            if (e > localmax) localmax = e;
        }
        run += h[k];
    }
    if (localmax) atomicMax(&smax, localmax);
    __syncthreads();
    if (t == 0) g_candcnt[b] = smax;
}

// ---------------- K3: scatter candidates (cursor = basedyn) ----------------
__global__ void k_scatter() {
    int g = blockIdx.x * blockDim.x + threadIdx.x;
    if (g >= BATCH * NPTS) return;
    int b = g >> 15, i = g & (NPTS - 1);
    unsigned long long key = g_keyfull[b][i];
    int bucket = (int)(key >> 48);
    if (g_base[b][bucket] < KSEL) {
        int pos = atomicAdd(&g_basedyn[b][bucket], 1);  // pos in [base, base+cnt)
        g_cand[b][pos] = key;                           // < NPTS always
    }
}

// ---------------- K4: exact rank + fused gather ----------------
__global__ void k_rankgather(const float* __restrict__ boxes,
                             const float* __restrict__ cls) {
    int g = blockIdx.x * blockDim.x + threadIdx.x;
    if (g >= BATCH * NPTS) return;
    int b = g >> 15, slot = g & (NPTS - 1);
    if (slot >= g_candcnt[b]) return;
    unsigned long long key = g_cand[b][slot];
    int bucket = (int)(key >> 48);
    int segbase = g_base[b][bucket];
    int segcnt  = g_hist[b][bucket];
    int rank = segbase;
    if (segcnt > 1) {
        const unsigned long long* seg = &g_cand[b][segbase];
        int gt = 0;
        for (int m = 0; m < segcnt; m++) gt += (__ldg(&seg[m]) > key);
        rank += gt;                        // keys distinct -> unique ranks
    }
    if (rank >= KSEL) return;

    int idx = (int)(0xFFFFFFFFu - (unsigned)key);

    const float* bx = boxes + ((size_t)b * NPTS + idx) * 7;
    float v0 = bx[0], v1 = bx[1], v2 = bx[2], v3 = bx[3],
          v4 = bx[4], v5 = bx[5], v6 = bx[6];
    float* ro = &g_rois[b][rank][0];
    ro[0] = v0; ro[1] = v1; ro[2] = v2; ro[3] = v3;
    ro[4] = v4; ro[5] = v5; ro[6] = v6;

    const float* cp = cls + ((size_t)b * NPTS + idx) * NCLS;
    float c0 = cp[0], c1 = cp[1], c2 = cp[2];
    float s = c0; int lab = 0;
    if (c1 > s) { s = c1; lab = 1; }
    if (c2 > s) { s = c2; lab = 2; }
    g_scores[b][rank] = s;
    g_labels[b][rank] = (unsigned char)lab;

    float hx = __fmul_rn(0.5f, v3), hy = __fmul_rn(0.5f, v4);
    float x1 = __fsub_rn(v0, hx), x2 = __fadd_rn(v0, hx);
    float y1 = __fsub_rn(v1, hy), y2 = __fadd_rn(v1, hy);
    g_box4[b][rank] = make_float4(x1, y1, x2, y2);
    g_area[b][rank] = __fmul_rn(v3, v4);
}

// ---------------- K5: stage-0 suppression mask (first 1024 boxes) ----------------
// compact layout g_mask0[b][row*16 + colword], upper-tri blocks only
__global__ void __launch_bounds__(64)
k_mask0() {
    int cb = blockIdx.x, rb = blockIdx.y, b = blockIdx.z;
    if (cb < rb) return;

    __shared__ float4 sb[64];
    __shared__ float  sa[64];
    int t = threadIdx.x;
    sb[t] = g_box4[b][cb * 64 + t];
    sa[t] = g_area[b][cb * 64 + t];
    __syncthreads();

    int i = rb * 64 + t;
    float4 me = g_box4[b][i];
    float  a  = g_area[b][i];
    unsigned long long m = 0;
    int j0 = (cb == rb) ? (t + 1) : 0;     // only j > i suppressed
    for (int jj = j0; jj < 64; jj++) {
        if (iou_gt(me, a, sb[jj], sa[jj])) m |= (1ull << jj);
    }
    g_mask0[b][(size_t)i * NW1 + cb] = m;
}

// ---------------- K6: fused scan (stage 0) + on-the-fly full fallback ----------
// 1024 threads per batch. Stage 0: one coalesced load per thread per word from
// g_mask0, software-pipelined one word ahead; serial greedy on thread 0; smem
// OR-reduction. If >=512 survive -> done. Else: full 4096-box NMS with IOUs
// recomputed from smem boxes (correct, never taken on this data).
__global__ void __launch_bounds__(1024)
k_scan_full() {
    int b = blockIdx.x, tid = threadIdx.x;
    extern __shared__ unsigned char dsm[];
    float4* sbox  = (float4*)dsm;                    // 4096 * 16B
    float*  sarea = (float*)(dsm + KSEL * 16);       // 4096 * 4B

    __shared__ unsigned long long remv[NWORDS];
    __shared__ unsigned long long acc_s[NWORDS];
    __shared__ unsigned long long diag[64];
    __shared__ unsigned long long spart[1088];       // stage0: r*17+c ; fb: q*65+c
    __shared__ unsigned long long red[4][16];
    __shared__ int s_fb;

    if (tid < NWORDS) remv[tid] = 0ull;
    __syncthreads();

    // ---------- stage 0 ----------
    const unsigned long long* M0 = g_mask0[b];
    int c16 = tid & 15, r16 = tid >> 4;              // word, row-in-word
    unsigned long long m = M0[(size_t)r16 * NW1 + c16];   // word 0 rows

    for (int w = 0; w < NW1; w++) {
        if (c16 == w) diag[r16] = m;                 // diagonal comes free
        __syncthreads();
        if (tid == 0) {
            unsigned long long rem = remv[w], acc = 0ull;
            unsigned long long dn = diag[0];
#pragma unroll
            for (int bit = 0; bit < 64; bit++) {
                unsigned long long d = dn;
                if (bit < 63) dn = diag[bit + 1];
                if (!((rem >> bit) & 1ull)) { acc |= (1ull << bit); rem |= d; }
            }
            acc_s[w] = acc;
        }
        // prefetch next word while serial greedy runs
        unsigned long long mn = 0ull;
        if (w + 1 < NW1) mn = M0[(size_t)((w + 1) * 64 + r16) * NW1 + c16];
        __syncthreads();

        unsigned long long acc = acc_s[w];
        spart[r16 * 17 + c16] = ((acc >> r16) & 1ull) ? m : 0ull;
        __syncthreads();
        if (tid < 64) {
            int c = tid & 15, q = tid >> 4;
            unsigned long long v = 0ull;
#pragma unroll
            for (int k = 0; k < 16; k++) v |= spart[(q * 16 + k) * 17 + c];
            red[q][c] = v;
        }
        __syncthreads();
        if (tid < 16)
            remv[tid] |= red[0][tid] | red[1][tid] | red[2][tid] | red[3][tid];
        __syncthreads();
        m = mn;
    }

    if (tid == 0) {
        int cnt = 0;
        for (int w = 0; w < NW1; w++) cnt += __popcll(acc_s[w]);
        s_fb = (cnt < KPOST);
    }
    __syncthreads();

    if (!s_fb) {
        if (tid < NWORDS) g_accept[b][tid] = (tid < NW1) ? acc_s[tid] : 0ull;
        return;
    }

    // ---------- fallback: full 4096 on-the-fly NMS (never taken normally) ----
    for (int i = tid; i < KSEL; i += 1024) {
        sbox[i]  = g_box4[b][i];
        sarea[i] = g_area[b][i];
    }
    if (tid < NWORDS) remv[tid] = 0ull;
    __syncthreads();

    int qg = tid >> 6, colw = tid & 63;
    for (int w = 0; w < NWORDS; w++) {
        if (tid < 64) {                              // diag block on the fly
            int i = w * 64 + tid;
            float4 A = sbox[i]; float aA = sarea[i];
            unsigned long long d = 0ull;
            for (int j = tid + 1; j < 64; j++) {
                int j2 = w * 64 + j;
                if (iou_gt(A, aA, sbox[j2], sarea[j2])) d |= (1ull << j);
            }
            diag[tid] = d;
        }
        __syncthreads();
        if (tid == 0) {
            unsigned long long rem = remv[w], acc = 0ull;
#pragma unroll
            for (int bit = 0; bit < 64; bit++) {
                if (!((rem >> bit) & 1ull)) { acc |= (1ull << bit); rem |= diag[bit]; }
            }
            acc_s[w] = acc;
        }
        __syncthreads();

        unsigned long long acc = acc_s[w];
        unsigned long long p = 0ull;
        if (colw > w) {
#pragma unroll
            for (int rr = 0; rr < 4; rr++) {
                int rbit = qg + rr * 16;
                if ((acc >> rbit) & 1ull) {
                    int i = w * 64 + rbit;
                    float4 A = sbox[i]; float aA = sarea[i];
                    unsigned long long mm = 0ull;
                    for (int j = 0; j < 64; j++) {
                        int j2 = colw * 64 + j;
                        if (iou_gt(A, aA, sbox[j2], sarea[j2])) mm |= (1ull << j);
                    }
                    p |= mm;
                }
            }
        }
        spart[qg * 65 + colw] = p;
        __syncthreads();
        if (tid < 64) {
            unsigned long long r = remv[tid];
#pragma unroll
            for (int k = 0; k < 16; k++) r |= spart[k * 65 + tid];
            remv[tid] = r;
        }
        __syncthreads();
    }
    if (tid < NWORDS) g_accept[b][tid] = acc_s[tid];
}

// ---------------- K7: zero output slice + compact ----------------
__global__ void __launch_bounds__(512)
k_compact(float* __restrict__ out) {
    int b = blockIdx.x, t = threadIdx.x;

    // zero this batch's output slice (d_out is poisoned)
    float* rbase = out + b * KPOST * 7;
    for (int e = t; e < KPOST * 7; e += 512) rbase[e] = 0.0f;
    if (t < KPOST) {
        out[SC_OFF + b * KPOST + t] = 0.0f;
        out[LB_OFF + b * KPOST + t] = 0.0f;
    }

    __shared__ unsigned long long acc[NWORDS];
    __shared__ int pref[NWORDS];
    if (t < NWORDS) acc[t] = g_accept[b][t];
    __syncthreads();
    if (t == 0) {
        int s = 0;
        for (int w = 0; w < NWORDS; w++) { pref[w] = s; s += __popcll(acc[w]); }
    }
    __syncthreads();

    if (t < NWORDS) {
        unsigned long long a = acc[t];
        int rank = pref[t];
        while (a && rank < KPOST) {
            int bit = __ffsll((long long)a) - 1;
            a &= a - 1;
            int i = t * 64 + bit;
            const float* ro = &g_rois[b][i][0];
            int obase = (b * KPOST + rank) * 7;
#pragma unroll
            for (int c = 0; c < 7; c++) out[obase + c] = ro[c];
            out[SC_OFF + b * KPOST + rank] = g_scores[b][i];
            out[LB_OFF + b * KPOST + rank] = (float)(g_labels[b][i] + 1);
            rank++;
        }
    }
}

// ---------------- launch ----------------
extern "C" void kernel_launch(void* const* d_in, const int* in_sizes, int n_in,
                              void* d_out, int out_size) {
    const float* boxes = (const float*)d_in[0];
    const float* cls   = (const float*)d_in[1];
    if (n_in >= 2 && in_sizes[0] == BATCH * NPTS * NCLS) {
        boxes = (const float*)d_in[1];
        cls   = (const float*)d_in[0];
    }
    float* out = (float*)d_out;

    const int NTOT = BATCH * NPTS;
    const int DSM = KSEL * 16 + KSEL * 4;    // 80 KB boxes for fallback

    static int smem_set = 0;
    if (!smem_set) {
        cudaFuncSetAttribute(k_scan_full,
                             cudaFuncAttributeMaxDynamicSharedMemorySize, DSM);
        smem_set = 1;
    }

    k_zero_state<<<256, 256>>>();
    k_keys_hist<<<NTOT / 256, 256>>>(cls);
    k_scan_hist<<<BATCH, 1024>>>();
    k_scatter<<<NTOT / 256, 256>>>();
    k_rankgather<<<NTOT / 256, 256>>>(boxes, cls);
    k_mask0<<<dim3(NW1, NW1, BATCH), 64>>>();
    k_scan_full<<<BATCH, 1024, DSM>>>();
    k_compact<<<BATCH, 512>>>(out);
}